// round 2
// baseline (speedup 1.0000x reference)
#include <cuda_runtime.h>
#include <cuda_bf16.h>

#define HH 512
#define WW 512
#define NPIX (HH*WW)
#define NIMG 32
#define SMOOTHF 1e-5f
#define KF 5            // fused skeletonize iterations per pass
#define HALO_C 12       // column halo per side (>= 2*KF, multiple of 4)
#define OWNC 104        // owned columns per warp window (128 - 2*HALO_C)
#define CTILES 5        // ceil(512/104)
#define RB 128          // rows per band
#define NBANDS 4
#define LAG (2*KF)      // pipeline row lag = 10
#define NSTEPS (RB + 2*LAG)  // 148

// Scratch (device globals: no allocation allowed)
__device__ float g_tmp [2][NIMG*NPIX];   // after iterations 1..5
__device__ float g_skel[2][NIMG*NPIX];   // after iterations 6..10
__device__ float g_acc [NIMG][8];        // 0:sp 1:st 2:spt 3:ssp 4:sst 5:sspt

__device__ __forceinline__ float sigf(float x){
    return __fdividef(1.0f, 1.0f + __expf(-x));
}

__global__ void k_init(){
    int i = blockIdx.x*blockDim.x + threadIdx.x;
    if (i < NIMG*8) ((float*)g_acc)[i] = 0.0f;
}

// ---------------- dice sums: sigmoid(logits) vs target ----------------
__global__ void k_dice(const float* __restrict__ logits, const float* __restrict__ target){
    int img = blockIdx.x;
    size_t base = (size_t)img*NPIX + (size_t)blockIdx.y*(NPIX/32);
    const float4* Lp = (const float4*)(logits + base);
    const float4* Tp = (const float4*)(target + base);
    int tid = threadIdx.x;
    float sp=0.f, st=0.f, spt=0.f;
    #pragma unroll
    for (int i = 0; i < 8; i++){
        float4 l = Lp[i*256 + tid];
        float4 t = Tp[i*256 + tid];
        float p;
        p = sigf(l.x); sp += p; st += t.x; spt += p*t.x;
        p = sigf(l.y); sp += p; st += t.y; spt += p*t.y;
        p = sigf(l.z); sp += p; st += t.z; spt += p*t.z;
        p = sigf(l.w); sp += p; st += t.w; spt += p*t.w;
    }
    #pragma unroll
    for (int o=16;o;o>>=1){
        sp  += __shfl_down_sync(0xffffffffu, sp , o);
        st  += __shfl_down_sync(0xffffffffu, st , o);
        spt += __shfl_down_sync(0xffffffffu, spt, o);
    }
    if ((tid & 31) == 0){
        atomicAdd(&g_acc[img][0], sp);
        atomicAdd(&g_acc[img][1], st);
        atomicAdd(&g_acc[img][2], spt);
    }
}

// ---------------- skeleton dice sums ----------------
__global__ void k_sdice(){
    int img = blockIdx.x;
    size_t base = (size_t)img*NPIX + (size_t)blockIdx.y*(NPIX/32);
    const float4* Pp = (const float4*)(g_skel[0] + base);
    const float4* Tp = (const float4*)(g_skel[1] + base);
    int tid = threadIdx.x;
    float sp=0.f, st=0.f, spt=0.f;
    #pragma unroll
    for (int i = 0; i < 8; i++){
        float4 p = Pp[i*256 + tid];
        float4 t = Tp[i*256 + tid];
        sp  += (p.x+p.y)+(p.z+p.w);
        st  += (t.x+t.y)+(t.z+t.w);
        spt += (p.x*t.x + p.y*t.y) + (p.z*t.z + p.w*t.w);
    }
    #pragma unroll
    for (int o=16;o;o>>=1){
        sp  += __shfl_down_sync(0xffffffffu, sp , o);
        st  += __shfl_down_sync(0xffffffffu, st , o);
        spt += __shfl_down_sync(0xffffffffu, spt, o);
    }
    if ((tid & 31) == 0){
        atomicAdd(&g_acc[img][3], sp);
        atomicAdd(&g_acc[img][4], st);
        atomicAdd(&g_acc[img][5], spt);
    }
}

// ---------------- fused 5-iteration soft skeletonize pass ----------------
// Per-warp register pipeline: each lane owns 4 contiguous columns, rows
// streamed top->bottom, one pipeline stage per iteration (row lag 2/stage).
// SAME padding emulated with S=+INF / E=-INF invariants at OOB rows/cols.
template<bool FIRST>
__global__ void __launch_bounds__(128) k_skel(const float* __restrict__ logits,
                                              const float* __restrict__ target){
    const float PINF = __int_as_float(0x7f800000);
    const float NINF = __int_as_float(0xff800000);

    int gw   = blockIdx.x * 4 + (threadIdx.x >> 5);
    int lane = threadIdx.x & 31;
    int band = gw & 3;  int q = gw >> 2;
    int ct   = q % CTILES; q /= CTILES;
    int img  = q & 31;  int tens = q >> 5;

    const float* __restrict__ src;
    float* __restrict__ dst;
    if (FIRST){
        src = (tens ? target : logits) + (size_t)img*NPIX;
        dst = g_tmp[tens] + (size_t)img*NPIX;
    } else {
        src = g_tmp[tens] + (size_t)img*NPIX;
        dst = g_skel[tens] + (size_t)img*NPIX;
    }

    int r0 = band * RB;
    int c0 = ct*OWNC - HALO_C;
    int gc = c0 + (lane<<2);                 // lane's 4 global cols (mult of 4)
    bool colok = (gc >= 0) && (gc < WW);     // whole float4 in or out
    bool owned = (lane >= HALO_C/4) && (lane < (HALO_C+OWNC)/4) && colok;

    // Rolling state per stage: S rows (xr-1, xr-2), E rows (xr-2, xr-3)
    float s1[KF][4], s2[KF][4], e2[KF][4], e3[KF][4];
    #pragma unroll
    for (int j = 0; j < KF; j++)
        #pragma unroll
        for (int v = 0; v < 4; v++){
            s1[j][v]=PINF; s2[j][v]=PINF; e2[j][v]=NINF; e3[j][v]=NINF;
        }

    for (int step = 0; step < NSTEPS; step++){
        int x = r0 - LAG + step;             // fed row for stage 0
        float cur[4];
        if (colok && (unsigned)x < (unsigned)HH){
            float4 t4 = *(const float4*)(src + (size_t)x*WW + gc);
            if (FIRST && tens == 0){
                t4.x = sigf(t4.x); t4.y = sigf(t4.y);
                t4.z = sigf(t4.z); t4.w = sigf(t4.w);
            }
            cur[0]=t4.x; cur[1]=t4.y; cur[2]=t4.z; cur[3]=t4.w;
        } else {
            cur[0]=PINF; cur[1]=PINF; cur[2]=PINF; cur[3]=PINF;
        }

        #pragma unroll
        for (int j = 0; j < KF; j++){
            int xr = x - 2*j;                // this stage's incoming row index
            // ---- erode: E[xr-1] = min3x3(S), separable ----
            float vm0 = fminf(s2[j][0], fminf(s1[j][0], cur[0]));
            float vm1 = fminf(s2[j][1], fminf(s1[j][1], cur[1]));
            float vm2 = fminf(s2[j][2], fminf(s1[j][2], cur[2]));
            float vm3 = fminf(s2[j][3], fminf(s1[j][3], cur[3]));
            float Lm = __shfl_up_sync  (0xffffffffu, vm3, 1);
            float Rm = __shfl_down_sync(0xffffffffu, vm0, 1);
            float m01 = fminf(vm0, vm1), m12 = fminf(vm1, vm2), m23 = fminf(vm2, vm3);
            float en0 = fminf(Lm,  m01);
            float en1 = fminf(m01, vm2);
            float en2 = fminf(m12, vm3);
            float en3 = fminf(m23, Rm);
            int er = xr - 1;
            if (!(colok && (unsigned)er < (unsigned)HH)){
                en0 = NINF; en1 = NINF; en2 = NINF; en3 = NINF;
            }
            // ---- dilate: T[xr-2] = max3x3(E) over rows xr-3..xr-1 ----
            float tx0 = fmaxf(e3[j][0], fmaxf(e2[j][0], en0));
            float tx1 = fmaxf(e3[j][1], fmaxf(e2[j][1], en1));
            float tx2 = fmaxf(e3[j][2], fmaxf(e2[j][2], en2));
            float tx3 = fmaxf(e3[j][3], fmaxf(e2[j][3], en3));
            float Lx = __shfl_up_sync  (0xffffffffu, tx3, 1);
            float Rx = __shfl_down_sync(0xffffffffu, tx0, 1);
            float M01 = fmaxf(tx0, tx1), M12 = fmaxf(tx1, tx2), M23 = fmaxf(tx2, tx3);
            float T0 = fmaxf(Lx,  M01);
            float T1 = fmaxf(M01, tx2);
            float T2 = fmaxf(M12, tx3);
            float T3 = fmaxf(M23, Rx);
            // ---- update: S'[xr-2] = S - (S-E)*T  (clip is a no-op) ----
            int orow = xr - 2;
            float o0 = fmaf(-(s2[j][0]-e2[j][0]), T0, s2[j][0]);
            float o1 = fmaf(-(s2[j][1]-e2[j][1]), T1, s2[j][1]);
            float o2 = fmaf(-(s2[j][2]-e2[j][2]), T2, s2[j][2]);
            float o3 = fmaf(-(s2[j][3]-e2[j][3]), T3, s2[j][3]);
            if (!(colok && (unsigned)orow < (unsigned)HH)){
                o0 = PINF; o1 = PINF; o2 = PINF; o3 = PINF;
            }
            // ---- rotate state; stage output becomes next stage input ----
            #pragma unroll
            for (int v = 0; v < 4; v++){
                s2[j][v] = s1[j][v];
                e3[j][v] = e2[j][v];
            }
            s1[j][0] = cur[0]; s1[j][1] = cur[1]; s1[j][2] = cur[2]; s1[j][3] = cur[3];
            e2[j][0] = en0;    e2[j][1] = en1;    e2[j][2] = en2;    e2[j][3] = en3;
            cur[0] = o0; cur[1] = o1; cur[2] = o2; cur[3] = o3;
        }

        if (owned && step >= 2*LAG){
            int orow = x - LAG;              // in [r0, r0+RB)
            *(float4*)(dst + (size_t)orow*WW + gc) =
                make_float4(cur[0], cur[1], cur[2], cur[3]);
        }
    }
}

// ---------------- final reduction ----------------
__global__ void k_fin(float* __restrict__ out){
    int i = threadIdx.x;   // 32 threads, one per image
    float d  = (2.0f*g_acc[i][2] + SMOOTHF) / (g_acc[i][0] + g_acc[i][1] + SMOOTHF);
    float sd = (2.0f*g_acc[i][5] + SMOOTHF) / (g_acc[i][3] + g_acc[i][4] + SMOOTHF);
    #pragma unroll
    for (int o=16;o;o>>=1){
        d  += __shfl_down_sync(0xffffffffu, d , o);
        sd += __shfl_down_sync(0xffffffffu, sd, o);
    }
    if (i == 0){
        float dice  = d  * (1.0f/32.0f);
        float sdice = sd * (1.0f/32.0f);
        out[0] = 0.5f*(1.0f - dice) + 0.5f*(1.0f - sdice);
        out[1] = dice;
        out[2] = sdice;
    }
}

extern "C" void kernel_launch(void* const* d_in, const int* in_sizes, int n_in,
                              void* d_out, int out_size){
    const float* logits = (const float*)d_in[0];
    const float* target = (const float*)d_in[1];
    float* out = (float*)d_out;

    int nwarps = 2 * NIMG * CTILES * NBANDS;       // 1280
    int nblocks = nwarps / 4;                      // 320

    k_init<<<1, 256>>>();
    k_dice<<<dim3(NIMG, 32), 256>>>(logits, target);
    k_skel<true ><<<nblocks, 128>>>(logits, target);
    k_skel<false><<<nblocks, 128>>>(logits, target);
    k_sdice<<<dim3(NIMG, 32), 256>>>();
    k_fin<<<1, 32>>>(out);
    (void)in_sizes; (void)n_in; (void)out_size;
}

// round 3
// speedup vs baseline: 1.1883x; 1.1883x over previous
#include <cuda_runtime.h>
#include <cuda_bf16.h>

#define HH 512
#define WW 512
#define NPIX (HH*WW)
#define NIMG 32
#define SMOOTHF 1e-5f
#define KF 5            // fused skeletonize iterations per pass
#define HALO_C 12       // column halo per side (>= 2*KF, multiple of 4)
#define OWNC 104        // owned columns per warp window (128 - 2*HALO_C)
#define CTILES 5        // ceil(512/104)
#define RB 64           // rows per band
#define NBANDS 8
#define LAG (2*KF)      // pipeline row lag = 10
#define NSTEPS (RB + 2*LAG)  // 84

// Scratch (device globals: no allocation allowed)
__device__ float g_tmp [2][NIMG*NPIX];   // after iterations 1..5
__device__ float g_skel[2][NIMG*NPIX];   // after iterations 6..10
__device__ float g_acc [NIMG][8];        // 0:sp 1:st 2:spt 3:ssp 4:sst 5:sspt

__device__ __forceinline__ float sigf(float x){
    return __fdividef(1.0f, 1.0f + __expf(-x));
}

__global__ void k_init(){
    int i = blockIdx.x*blockDim.x + threadIdx.x;
    if (i < NIMG*8) ((float*)g_acc)[i] = 0.0f;
}

// ---------------- dice sums: sigmoid(logits) vs target ----------------
__global__ void k_dice(const float* __restrict__ logits, const float* __restrict__ target){
    int img = blockIdx.x;
    size_t base = (size_t)img*NPIX + (size_t)blockIdx.y*(NPIX/32);
    const float4* Lp = (const float4*)(logits + base);
    const float4* Tp = (const float4*)(target + base);
    int tid = threadIdx.x;
    float sp=0.f, st=0.f, spt=0.f;
    #pragma unroll
    for (int i = 0; i < 8; i++){
        float4 l = Lp[i*256 + tid];
        float4 t = Tp[i*256 + tid];
        float p;
        p = sigf(l.x); sp += p; st += t.x; spt += p*t.x;
        p = sigf(l.y); sp += p; st += t.y; spt += p*t.y;
        p = sigf(l.z); sp += p; st += t.z; spt += p*t.z;
        p = sigf(l.w); sp += p; st += t.w; spt += p*t.w;
    }
    #pragma unroll
    for (int o=16;o;o>>=1){
        sp  += __shfl_down_sync(0xffffffffu, sp , o);
        st  += __shfl_down_sync(0xffffffffu, st , o);
        spt += __shfl_down_sync(0xffffffffu, spt, o);
    }
    if ((tid & 31) == 0){
        atomicAdd(&g_acc[img][0], sp);
        atomicAdd(&g_acc[img][1], st);
        atomicAdd(&g_acc[img][2], spt);
    }
}

// ---------------- skeleton dice sums ----------------
__global__ void k_sdice(){
    int img = blockIdx.x;
    size_t base = (size_t)img*NPIX + (size_t)blockIdx.y*(NPIX/32);
    const float4* Pp = (const float4*)(g_skel[0] + base);
    const float4* Tp = (const float4*)(g_skel[1] + base);
    int tid = threadIdx.x;
    float sp=0.f, st=0.f, spt=0.f;
    #pragma unroll
    for (int i = 0; i < 8; i++){
        float4 p = Pp[i*256 + tid];
        float4 t = Tp[i*256 + tid];
        sp  += (p.x+p.y)+(p.z+p.w);
        st  += (t.x+t.y)+(t.z+t.w);
        spt += (p.x*t.x + p.y*t.y) + (p.z*t.z + p.w*t.w);
    }
    #pragma unroll
    for (int o=16;o;o>>=1){
        sp  += __shfl_down_sync(0xffffffffu, sp , o);
        st  += __shfl_down_sync(0xffffffffu, st , o);
        spt += __shfl_down_sync(0xffffffffu, spt, o);
    }
    if ((tid & 31) == 0){
        atomicAdd(&g_acc[img][3], sp);
        atomicAdd(&g_acc[img][4], st);
        atomicAdd(&g_acc[img][5], spt);
    }
}

// ---------------- fused 5-iteration soft skeletonize pass ----------------
// Per-warp register pipeline: each lane owns 4 contiguous columns, rows
// streamed top->bottom, one pipeline stage per iteration (row lag 2/stage).
// SAME padding emulated with S=+INF / E=-INF invariants at OOB rows/cols.
template<bool FIRST>
__global__ void __launch_bounds__(128, 4) k_skel(const float* __restrict__ logits,
                                                 const float* __restrict__ target){
    const float PINF = __int_as_float(0x7f800000);
    const float NINF = __int_as_float(0xff800000);

    int gw   = blockIdx.x * 4 + (threadIdx.x >> 5);
    int lane = threadIdx.x & 31;
    int band = gw & 7;  int q = gw >> 3;
    int ct   = q % CTILES; q /= CTILES;
    int img  = q & 31;  int tens = q >> 5;

    const float* __restrict__ src;
    float* __restrict__ dst;
    if (FIRST){
        src = (tens ? target : logits) + (size_t)img*NPIX;
        dst = g_tmp[tens] + (size_t)img*NPIX;
    } else {
        src = g_tmp[tens] + (size_t)img*NPIX;
        dst = g_skel[tens] + (size_t)img*NPIX;
    }

    int r0 = band * RB;
    int c0 = ct*OWNC - HALO_C;
    int gc = c0 + (lane<<2);                 // lane's 4 global cols (mult of 4)
    bool colok = (gc >= 0) && (gc < WW);     // whole float4 in or out
    bool owned = (lane >= HALO_C/4) && (lane < (HALO_C+OWNC)/4) && colok;

    // Rolling state per stage: S rows (xr-1, xr-2), E rows (xr-2, xr-3)
    float s1[KF][4], s2[KF][4], e2[KF][4], e3[KF][4];
    #pragma unroll
    for (int j = 0; j < KF; j++)
        #pragma unroll
        for (int v = 0; v < 4; v++){
            s1[j][v]=PINF; s2[j][v]=PINF; e2[j][v]=NINF; e3[j][v]=NINF;
        }

    // software-pipelined row fetch: nxt holds the row for the upcoming step
    float nxt[4];
    {
        int x = r0 - LAG;
        if (colok && (unsigned)x < (unsigned)HH){
            float4 t4 = *(const float4*)(src + (size_t)x*WW + gc);
            if (FIRST && tens == 0){
                t4.x = sigf(t4.x); t4.y = sigf(t4.y);
                t4.z = sigf(t4.z); t4.w = sigf(t4.w);
            }
            nxt[0]=t4.x; nxt[1]=t4.y; nxt[2]=t4.z; nxt[3]=t4.w;
        } else {
            nxt[0]=PINF; nxt[1]=PINF; nxt[2]=PINF; nxt[3]=PINF;
        }
    }

    for (int step = 0; step < NSTEPS; step++){
        int x = r0 - LAG + step;             // fed row for stage 0
        float cur[4] = {nxt[0], nxt[1], nxt[2], nxt[3]};

        // prefetch next step's row before entering the dependency chain
        int xn = x + 1;
        if (colok && (unsigned)xn < (unsigned)HH){
            float4 t4 = *(const float4*)(src + (size_t)xn*WW + gc);
            if (FIRST && tens == 0){
                t4.x = sigf(t4.x); t4.y = sigf(t4.y);
                t4.z = sigf(t4.z); t4.w = sigf(t4.w);
            }
            nxt[0]=t4.x; nxt[1]=t4.y; nxt[2]=t4.z; nxt[3]=t4.w;
        } else {
            nxt[0]=PINF; nxt[1]=PINF; nxt[2]=PINF; nxt[3]=PINF;
        }

        #pragma unroll
        for (int j = 0; j < KF; j++){
            int xr = x - 2*j;                // this stage's incoming row index
            // ---- erode: E[xr-1] = min3x3(S), separable ----
            float vm0 = fminf(s2[j][0], fminf(s1[j][0], cur[0]));
            float vm1 = fminf(s2[j][1], fminf(s1[j][1], cur[1]));
            float vm2 = fminf(s2[j][2], fminf(s1[j][2], cur[2]));
            float vm3 = fminf(s2[j][3], fminf(s1[j][3], cur[3]));
            float Lm = __shfl_up_sync  (0xffffffffu, vm3, 1);
            float Rm = __shfl_down_sync(0xffffffffu, vm0, 1);
            float m01 = fminf(vm0, vm1), m12 = fminf(vm1, vm2), m23 = fminf(vm2, vm3);
            float en0 = fminf(Lm,  m01);
            float en1 = fminf(m01, vm2);
            float en2 = fminf(m12, vm3);
            float en3 = fminf(m23, Rm);
            int er = xr - 1;
            if (!(colok && (unsigned)er < (unsigned)HH)){
                en0 = NINF; en1 = NINF; en2 = NINF; en3 = NINF;
            }
            // ---- dilate: T[xr-2] = max3x3(E) over rows xr-3..xr-1 ----
            float tx0 = fmaxf(e3[j][0], fmaxf(e2[j][0], en0));
            float tx1 = fmaxf(e3[j][1], fmaxf(e2[j][1], en1));
            float tx2 = fmaxf(e3[j][2], fmaxf(e2[j][2], en2));
            float tx3 = fmaxf(e3[j][3], fmaxf(e2[j][3], en3));
            float Lx = __shfl_up_sync  (0xffffffffu, tx3, 1);
            float Rx = __shfl_down_sync(0xffffffffu, tx0, 1);
            float M01 = fmaxf(tx0, tx1), M12 = fmaxf(tx1, tx2), M23 = fmaxf(tx2, tx3);
            float T0 = fmaxf(Lx,  M01);
            float T1 = fmaxf(M01, tx2);
            float T2 = fmaxf(M12, tx3);
            float T3 = fmaxf(M23, Rx);
            // ---- update: S'[xr-2] = S + (E-S)*T  (clip is a no-op) ----
            int orow = xr - 2;
            float o0 = fmaf(e2[j][0]-s2[j][0], T0, s2[j][0]);
            float o1 = fmaf(e2[j][1]-s2[j][1], T1, s2[j][1]);
            float o2 = fmaf(e2[j][2]-s2[j][2], T2, s2[j][2]);
            float o3 = fmaf(e2[j][3]-s2[j][3], T3, s2[j][3]);
            if (!(colok && (unsigned)orow < (unsigned)HH)){
                o0 = PINF; o1 = PINF; o2 = PINF; o3 = PINF;
            }
            // ---- rotate state; stage output becomes next stage input ----
            #pragma unroll
            for (int v = 0; v < 4; v++){
                s2[j][v] = s1[j][v];
                e3[j][v] = e2[j][v];
            }
            s1[j][0] = cur[0]; s1[j][1] = cur[1]; s1[j][2] = cur[2]; s1[j][3] = cur[3];
            e2[j][0] = en0;    e2[j][1] = en1;    e2[j][2] = en2;    e2[j][3] = en3;
            cur[0] = o0; cur[1] = o1; cur[2] = o2; cur[3] = o3;
        }

        if (owned && step >= 2*LAG){
            int orow = x - LAG;              // in [r0, r0+RB)
            *(float4*)(dst + (size_t)orow*WW + gc) =
                make_float4(cur[0], cur[1], cur[2], cur[3]);
        }
    }
}

// ---------------- final reduction ----------------
__global__ void k_fin(float* __restrict__ out){
    int i = threadIdx.x;   // 32 threads, one per image
    float d  = (2.0f*g_acc[i][2] + SMOOTHF) / (g_acc[i][0] + g_acc[i][1] + SMOOTHF);
    float sd = (2.0f*g_acc[i][5] + SMOOTHF) / (g_acc[i][3] + g_acc[i][4] + SMOOTHF);
    #pragma unroll
    for (int o=16;o;o>>=1){
        d  += __shfl_down_sync(0xffffffffu, d , o);
        sd += __shfl_down_sync(0xffffffffu, sd, o);
    }
    if (i == 0){
        float dice  = d  * (1.0f/32.0f);
        float sdice = sd * (1.0f/32.0f);
        out[0] = 0.5f*(1.0f - dice) + 0.5f*(1.0f - sdice);
        out[1] = dice;
        out[2] = sdice;
    }
}

extern "C" void kernel_launch(void* const* d_in, const int* in_sizes, int n_in,
                              void* d_out, int out_size){
    const float* logits = (const float*)d_in[0];
    const float* target = (const float*)d_in[1];
    float* out = (float*)d_out;

    int nwarps = 2 * NIMG * CTILES * NBANDS;       // 2560
    int nblocks = nwarps / 4;                      // 640

    k_init<<<1, 256>>>();
    k_dice<<<dim3(NIMG, 32), 256>>>(logits, target);
    k_skel<true ><<<nblocks, 128>>>(logits, target);
    k_skel<false><<<nblocks, 128>>>(logits, target);
    k_sdice<<<dim3(NIMG, 32), 256>>>();
    k_fin<<<1, 32>>>(out);
    (void)in_sizes; (void)n_in; (void)out_size;
}

// round 4
// speedup vs baseline: 1.2036x; 1.0129x over previous
#include <cuda_runtime.h>
#include <cuda_bf16.h>

#define HH 512
#define WW 512
#define NPIX (HH*WW)
#define NIMG 32
#define SMOOTHF 1e-5f
#define KF 5            // fused skeletonize iterations per pass
#define HALO_C 12       // column halo per side (>= 2*KF, multiple of 4)
#define OWNC 104        // owned columns per warp window (128 - 2*HALO_C)
#define CTILES 5        // ceil(512/104)
#define RB 64           // rows per band
#define NBANDS 8
#define LAG (2*KF)      // pipeline row lag = 10
#define NSTEPS (RB + 2*LAG)  // 84 (even -> exact 2-step unroll)
#define ALLM 0xffffffffu

// Scratch (device globals: no allocation allowed)
__device__ float g_tmp [2][NIMG*NPIX];   // after iterations 1..5
__device__ float g_skel[2][NIMG*NPIX];   // after iterations 6..10
__device__ float g_acc [NIMG][8];        // 0:sp 1:st 2:spt 3:ssp 4:sst 5:sspt

__device__ __forceinline__ float sigf(float x){
    return __fdividef(1.0f, 1.0f + __expf(-x));
}

__global__ void k_init(){
    int i = blockIdx.x*blockDim.x + threadIdx.x;
    if (i < NIMG*8) ((float*)g_acc)[i] = 0.0f;
}

// ---------------- dice sums: sigmoid(logits) vs target ----------------
__global__ void k_dice(const float* __restrict__ logits, const float* __restrict__ target){
    int img = blockIdx.x;
    size_t base = (size_t)img*NPIX + (size_t)blockIdx.y*(NPIX/32);
    const float4* Lp = (const float4*)(logits + base);
    const float4* Tp = (const float4*)(target + base);
    int tid = threadIdx.x;
    float sp=0.f, st=0.f, spt=0.f;
    #pragma unroll
    for (int i = 0; i < 8; i++){
        float4 l = Lp[i*256 + tid];
        float4 t = Tp[i*256 + tid];
        float p;
        p = sigf(l.x); sp += p; st += t.x; spt += p*t.x;
        p = sigf(l.y); sp += p; st += t.y; spt += p*t.y;
        p = sigf(l.z); sp += p; st += t.z; spt += p*t.z;
        p = sigf(l.w); sp += p; st += t.w; spt += p*t.w;
    }
    #pragma unroll
    for (int o=16;o;o>>=1){
        sp  += __shfl_down_sync(ALLM, sp , o);
        st  += __shfl_down_sync(ALLM, st , o);
        spt += __shfl_down_sync(ALLM, spt, o);
    }
    if ((tid & 31) == 0){
        atomicAdd(&g_acc[img][0], sp);
        atomicAdd(&g_acc[img][1], st);
        atomicAdd(&g_acc[img][2], spt);
    }
}

// ---------------- skeleton dice sums ----------------
__global__ void k_sdice(){
    int img = blockIdx.x;
    size_t base = (size_t)img*NPIX + (size_t)blockIdx.y*(NPIX/32);
    const float4* Pp = (const float4*)(g_skel[0] + base);
    const float4* Tp = (const float4*)(g_skel[1] + base);
    int tid = threadIdx.x;
    float sp=0.f, st=0.f, spt=0.f;
    #pragma unroll
    for (int i = 0; i < 8; i++){
        float4 p = Pp[i*256 + tid];
        float4 t = Tp[i*256 + tid];
        sp  += (p.x+p.y)+(p.z+p.w);
        st  += (t.x+t.y)+(t.z+t.w);
        spt += (p.x*t.x + p.y*t.y) + (p.z*t.z + p.w*t.w);
    }
    #pragma unroll
    for (int o=16;o;o>>=1){
        sp  += __shfl_down_sync(ALLM, sp , o);
        st  += __shfl_down_sync(ALLM, st , o);
        spt += __shfl_down_sync(ALLM, spt, o);
    }
    if ((tid & 31) == 0){
        atomicAdd(&g_acc[img][3], sp);
        atomicAdd(&g_acc[img][4], st);
        atomicAdd(&g_acc[img][5], spt);
    }
}

// One pipeline stage. sN[j] = S[xr-1], sO[j] = S[xr-2], eN[j] = E[xr-2],
// eO[j] = E[xr-3] where xr = x - 2j is the row fed into stage j this step.
// Writes cur -> sO slot (becomes next step's S[x-1]) and en -> eO slot
// (becomes next step's E[x-2]): rotation by role swap, zero MOVs.
#define STAGE(j, sN, sO, eN, eO)                                              \
{                                                                             \
    float vm0 = fminf(sO[j][0], fminf(sN[j][0], cur[0]));                     \
    float vm1 = fminf(sO[j][1], fminf(sN[j][1], cur[1]));                     \
    float vm2 = fminf(sO[j][2], fminf(sN[j][2], cur[2]));                     \
    float vm3 = fminf(sO[j][3], fminf(sN[j][3], cur[3]));                     \
    float Lm = __shfl_up_sync  (ALLM, vm3, 1);                                \
    float Rm = __shfl_down_sync(ALLM, vm0, 1);                                \
    float m01 = fminf(vm0, vm1), m12 = fminf(vm1, vm2), m23 = fminf(vm2, vm3);\
    float en0 = fminf(Lm,  m01);                                              \
    float en1 = fminf(m01, vm2);                                              \
    float en2 = fminf(m12, vm3);                                              \
    float en3 = fminf(m23, Rm);                                               \
    if (!(colok && (unsigned)(x - 2*(j) - 1) < (unsigned)HH)){                \
        en0 = NINF; en1 = NINF; en2 = NINF; en3 = NINF;                       \
    }                                                                         \
    float tx0 = fmaxf(eO[j][0], fmaxf(eN[j][0], en0));                        \
    float tx1 = fmaxf(eO[j][1], fmaxf(eN[j][1], en1));                        \
    float tx2 = fmaxf(eO[j][2], fmaxf(eN[j][2], en2));                        \
    float tx3 = fmaxf(eO[j][3], fmaxf(eN[j][3], en3));                        \
    float Lx = __shfl_up_sync  (ALLM, tx3, 1);                                \
    float Rx = __shfl_down_sync(ALLM, tx0, 1);                                \
    float M01 = fmaxf(tx0, tx1), M12 = fmaxf(tx1, tx2), M23 = fmaxf(tx2, tx3);\
    float T0 = fmaxf(Lx,  M01);                                               \
    float T1 = fmaxf(M01, tx2);                                               \
    float T2 = fmaxf(M12, tx3);                                               \
    float T3 = fmaxf(M23, Rx);                                                \
    float o0 = fmaf(eN[j][0]-sO[j][0], T0, sO[j][0]);                         \
    float o1 = fmaf(eN[j][1]-sO[j][1], T1, sO[j][1]);                         \
    float o2 = fmaf(eN[j][2]-sO[j][2], T2, sO[j][2]);                         \
    float o3 = fmaf(eN[j][3]-sO[j][3], T3, sO[j][3]);                         \
    if (!(colok && (unsigned)(x - 2*(j) - 2) < (unsigned)HH)){                \
        o0 = PINF; o1 = PINF; o2 = PINF; o3 = PINF;                           \
    }                                                                         \
    sO[j][0] = cur[0]; sO[j][1] = cur[1]; sO[j][2] = cur[2]; sO[j][3] = cur[3];\
    eO[j][0] = en0;    eO[j][1] = en1;    eO[j][2] = en2;    eO[j][3] = en3;  \
    cur[0] = o0; cur[1] = o1; cur[2] = o2; cur[3] = o3;                       \
}

// One full row-step (load-prefetch + 5 stages + store), with the given
// register roles. X is the row fed into stage 0.
#define DO_STEP(X, sN, sO, eN, eO)                                            \
{                                                                             \
    int x = (X);                                                              \
    float cur[4] = {nxt[0], nxt[1], nxt[2], nxt[3]};                          \
    int xn = x + 1;                                                           \
    if (colok && (unsigned)xn < (unsigned)HH){                                \
        float4 t4 = *(const float4*)(src + (size_t)xn*WW + gc);               \
        if (FIRST && tens == 0){                                              \
            t4.x = sigf(t4.x); t4.y = sigf(t4.y);                             \
            t4.z = sigf(t4.z); t4.w = sigf(t4.w);                             \
        }                                                                     \
        nxt[0]=t4.x; nxt[1]=t4.y; nxt[2]=t4.z; nxt[3]=t4.w;                   \
    } else {                                                                  \
        nxt[0]=PINF; nxt[1]=PINF; nxt[2]=PINF; nxt[3]=PINF;                   \
    }                                                                         \
    STAGE(0, sN, sO, eN, eO);                                                 \
    STAGE(1, sN, sO, eN, eO);                                                 \
    STAGE(2, sN, sO, eN, eO);                                                 \
    STAGE(3, sN, sO, eN, eO);                                                 \
    STAGE(4, sN, sO, eN, eO);                                                 \
    if (owned && x >= r0 + LAG){                                              \
        *(float4*)(dst + (size_t)(x - LAG)*WW + gc) =                         \
            make_float4(cur[0], cur[1], cur[2], cur[3]);                      \
    }                                                                         \
}

// ---------------- fused 5-iteration soft skeletonize pass ----------------
template<bool FIRST>
__global__ void __launch_bounds__(128, 4) k_skel(const float* __restrict__ logits,
                                                 const float* __restrict__ target){
    const float PINF = __int_as_float(0x7f800000);
    const float NINF = __int_as_float(0xff800000);

    int gw   = blockIdx.x * 4 + (threadIdx.x >> 5);
    int lane = threadIdx.x & 31;
    int band = gw & 7;  int q = gw >> 3;
    int ct   = q % CTILES; q /= CTILES;
    int img  = q & 31;  int tens = q >> 5;

    const float* __restrict__ src;
    float* __restrict__ dst;
    if (FIRST){
        src = (tens ? target : logits) + (size_t)img*NPIX;
        dst = g_tmp[tens] + (size_t)img*NPIX;
    } else {
        src = g_tmp[tens] + (size_t)img*NPIX;
        dst = g_skel[tens] + (size_t)img*NPIX;
    }

    int r0 = band * RB;
    int c0 = ct*OWNC - HALO_C;
    int gc = c0 + (lane<<2);                 // lane's 4 global cols (mult of 4)
    bool colok = (gc >= 0) && (gc < WW);     // whole float4 in or out
    bool owned = (lane >= HALO_C/4) && (lane < (HALO_C+OWNC)/4) && colok;

    // Ping-pong state per stage: roles swap every step.
    float sA[KF][4], sB[KF][4], eA[KF][4], eB[KF][4];
    #pragma unroll
    for (int j = 0; j < KF; j++)
        #pragma unroll
        for (int v = 0; v < 4; v++){
            sA[j][v]=PINF; sB[j][v]=PINF; eA[j][v]=NINF; eB[j][v]=NINF;
        }

    // software-pipelined row fetch: nxt holds the row for the upcoming step
    float nxt[4];
    {
        int x0 = r0 - LAG;
        if (colok && (unsigned)x0 < (unsigned)HH){
            float4 t4 = *(const float4*)(src + (size_t)x0*WW + gc);
            if (FIRST && tens == 0){
                t4.x = sigf(t4.x); t4.y = sigf(t4.y);
                t4.z = sigf(t4.z); t4.w = sigf(t4.w);
            }
            nxt[0]=t4.x; nxt[1]=t4.y; nxt[2]=t4.z; nxt[3]=t4.w;
        } else {
            nxt[0]=PINF; nxt[1]=PINF; nxt[2]=PINF; nxt[3]=PINF;
        }
    }

    for (int step = 0; step < NSTEPS; step += 2){
        DO_STEP(r0 - LAG + step,     sA, sB, eA, eB);
        DO_STEP(r0 - LAG + step + 1, sB, sA, eB, eA);
    }
}

// ---------------- final reduction ----------------
__global__ void k_fin(float* __restrict__ out){
    int i = threadIdx.x;   // 32 threads, one per image
    float d  = (2.0f*g_acc[i][2] + SMOOTHF) / (g_acc[i][0] + g_acc[i][1] + SMOOTHF);
    float sd = (2.0f*g_acc[i][5] + SMOOTHF) / (g_acc[i][3] + g_acc[i][4] + SMOOTHF);
    #pragma unroll
    for (int o=16;o;o>>=1){
        d  += __shfl_down_sync(ALLM, d , o);
        sd += __shfl_down_sync(ALLM, sd, o);
    }
    if (i == 0){
        float dice  = d  * (1.0f/32.0f);
        float sdice = sd * (1.0f/32.0f);
        out[0] = 0.5f*(1.0f - dice) + 0.5f*(1.0f - sdice);
        out[1] = dice;
        out[2] = sdice;
    }
}

extern "C" void kernel_launch(void* const* d_in, const int* in_sizes, int n_in,
                              void* d_out, int out_size){
    const float* logits = (const float*)d_in[0];
    const float* target = (const float*)d_in[1];
    float* out = (float*)d_out;

    int nwarps = 2 * NIMG * CTILES * NBANDS;       // 2560
    int nblocks = nwarps / 4;                      // 640

    k_init<<<1, 256>>>();
    k_dice<<<dim3(NIMG, 32), 256>>>(logits, target);
    k_skel<true ><<<nblocks, 128>>>(logits, target);
    k_skel<false><<<nblocks, 128>>>(logits, target);
    k_sdice<<<dim3(NIMG, 32), 256>>>();
    k_fin<<<1, 32>>>(out);
    (void)in_sizes; (void)n_in; (void)out_size;
}

// round 5
// speedup vs baseline: 1.2295x; 1.0215x over previous
#include <cuda_runtime.h>
#include <cuda_bf16.h>

#define HH 512
#define WW 512
#define NPIX (HH*WW)
#define NIMG 32
#define SMOOTHF 1e-5f
#define KF 5            // fused skeletonize iterations per pass
#define HALO_C 12       // column halo per side (>= 2*KF, multiple of 4)
#define OWNC 104        // owned columns per warp window (128 - 2*HALO_C)
#define CTILES 5        // ceil(512/104)
#define RB 128          // rows per band
#define NBANDS 4
#define LAGOUT 14       // output lag: 3*(KF-1)+2
#define NSTEPS 154      // RB + 25 + 1 (even, x0 = r0-11)
#define ALLM 0xffffffffu

// Scratch (device globals: no allocation allowed)
__device__ float g_tmp [2][NIMG*NPIX];   // after iterations 1..5
__device__ float g_skel[2][NIMG*NPIX];   // after iterations 6..10
__device__ float g_acc [NIMG][8];        // 0:sp 1:st 2:spt 3:ssp 4:sst 5:sspt

__device__ __forceinline__ float sigf(float x){
    return __fdividef(1.0f, 1.0f + __expf(-x));
}

__global__ void k_init(){
    int i = blockIdx.x*blockDim.x + threadIdx.x;
    if (i < NIMG*8) ((float*)g_acc)[i] = 0.0f;
}

// ---------------- dice sums: sigmoid(logits) vs target ----------------
__global__ void k_dice(const float* __restrict__ logits, const float* __restrict__ target){
    int img = blockIdx.x;
    size_t base = (size_t)img*NPIX + (size_t)blockIdx.y*(NPIX/32);
    const float4* Lp = (const float4*)(logits + base);
    const float4* Tp = (const float4*)(target + base);
    int tid = threadIdx.x;
    float sp=0.f, st=0.f, spt=0.f;
    #pragma unroll
    for (int i = 0; i < 8; i++){
        float4 l = Lp[i*256 + tid];
        float4 t = Tp[i*256 + tid];
        float p;
        p = sigf(l.x); sp += p; st += t.x; spt += p*t.x;
        p = sigf(l.y); sp += p; st += t.y; spt += p*t.y;
        p = sigf(l.z); sp += p; st += t.z; spt += p*t.z;
        p = sigf(l.w); sp += p; st += t.w; spt += p*t.w;
    }
    #pragma unroll
    for (int o=16;o;o>>=1){
        sp  += __shfl_down_sync(ALLM, sp , o);
        st  += __shfl_down_sync(ALLM, st , o);
        spt += __shfl_down_sync(ALLM, spt, o);
    }
    if ((tid & 31) == 0){
        atomicAdd(&g_acc[img][0], sp);
        atomicAdd(&g_acc[img][1], st);
        atomicAdd(&g_acc[img][2], spt);
    }
}

// ---------------- skeleton dice sums ----------------
__global__ void k_sdice(){
    int img = blockIdx.x;
    size_t base = (size_t)img*NPIX + (size_t)blockIdx.y*(NPIX/32);
    const float4* Pp = (const float4*)(g_skel[0] + base);
    const float4* Tp = (const float4*)(g_skel[1] + base);
    int tid = threadIdx.x;
    float sp=0.f, st=0.f, spt=0.f;
    #pragma unroll
    for (int i = 0; i < 8; i++){
        float4 p = Pp[i*256 + tid];
        float4 t = Tp[i*256 + tid];
        sp  += (p.x+p.y)+(p.z+p.w);
        st  += (t.x+t.y)+(t.z+t.w);
        spt += (p.x*t.x + p.y*t.y) + (p.z*t.z + p.w*t.w);
    }
    #pragma unroll
    for (int o=16;o;o>>=1){
        sp  += __shfl_down_sync(ALLM, sp , o);
        st  += __shfl_down_sync(ALLM, st , o);
        spt += __shfl_down_sync(ALLM, spt, o);
    }
    if ((tid & 31) == 0){
        atomicAdd(&g_acc[img][3], sp);
        atomicAdd(&g_acc[img][4], st);
        atomicAdd(&g_acc[img][5], spt);
    }
}

// One decoupled pipeline stage j. Fed row xr = x - 3j (value in CIN).
// State: sN[j] = In_j[xr-1], sO[j] = In_j[xr-2], eN[j] = E_j[xr-2],
// eO[j] = E_j[xr-3]. Computes E_j[xr-1] and O_j[xr-2] -> OUT.
// Rotation by role swap (zero MOVs): CIN -> sO slot, en -> eO slot.
#define STAGE(j, sN, sO, eN, eO, CIN, OUT)                                    \
{                                                                             \
    float vm0 = fminf(sO[j][0], fminf(sN[j][0], CIN[0]));                     \
    float vm1 = fminf(sO[j][1], fminf(sN[j][1], CIN[1]));                     \
    float vm2 = fminf(sO[j][2], fminf(sN[j][2], CIN[2]));                     \
    float vm3 = fminf(sO[j][3], fminf(sN[j][3], CIN[3]));                     \
    float Lm = __shfl_up_sync  (ALLM, vm3, 1);                                \
    float Rm = __shfl_down_sync(ALLM, vm0, 1);                                \
    float m01 = fminf(vm0, vm1), m12 = fminf(vm1, vm2), m23 = fminf(vm2, vm3);\
    float en0 = fminf(Lm,  m01);                                              \
    float en1 = fminf(m01, vm2);                                              \
    float en2 = fminf(m12, vm3);                                              \
    float en3 = fminf(m23, Rm);                                               \
    if (!(colok && (unsigned)(x - 3*(j) - 1) < (unsigned)HH)){                \
        en0 = NINF; en1 = NINF; en2 = NINF; en3 = NINF;                       \
    }                                                                         \
    float tx0 = fmaxf(eO[j][0], fmaxf(eN[j][0], en0));                        \
    float tx1 = fmaxf(eO[j][1], fmaxf(eN[j][1], en1));                        \
    float tx2 = fmaxf(eO[j][2], fmaxf(eN[j][2], en2));                        \
    float tx3 = fmaxf(eO[j][3], fmaxf(eN[j][3], en3));                        \
    float Lx = __shfl_up_sync  (ALLM, tx3, 1);                                \
    float Rx = __shfl_down_sync(ALLM, tx0, 1);                                \
    float M01 = fmaxf(tx0, tx1), M12 = fmaxf(tx1, tx2), M23 = fmaxf(tx2, tx3);\
    float T0 = fmaxf(Lx,  M01);                                               \
    float T1 = fmaxf(M01, tx2);                                               \
    float T2 = fmaxf(M12, tx3);                                               \
    float T3 = fmaxf(M23, Rx);                                                \
    float o0 = fmaf(eN[j][0]-sO[j][0], T0, sO[j][0]);                         \
    float o1 = fmaf(eN[j][1]-sO[j][1], T1, sO[j][1]);                         \
    float o2 = fmaf(eN[j][2]-sO[j][2], T2, sO[j][2]);                         \
    float o3 = fmaf(eN[j][3]-sO[j][3], T3, sO[j][3]);                         \
    if (!(colok && (unsigned)(x - 3*(j) - 2) < (unsigned)HH)){                \
        o0 = PINF; o1 = PINF; o2 = PINF; o3 = PINF;                           \
    }                                                                         \
    sO[j][0] = CIN[0]; sO[j][1] = CIN[1]; sO[j][2] = CIN[2]; sO[j][3] = CIN[3];\
    eO[j][0] = en0;    eO[j][1] = en1;    eO[j][2] = en2;    eO[j][3] = en3;  \
    OUT[0] = o0; OUT[1] = o1; OUT[2] = o2; OUT[3] = o3;                       \
}

// One full row-step. Stages evaluated in DESCENDING order so each stage j+1
// reads buf[j] (previous step's output of stage j) before stage j overwrites
// it. All 5 stages are mutually independent within a step -> ILP ~5.
#define DO_STEP(X, sN, sO, eN, eO)                                            \
{                                                                             \
    int x = (X);                                                              \
    float in0[4] = {nxt[0], nxt[1], nxt[2], nxt[3]};                          \
    int xn = x + 1;                                                           \
    if (colok && (unsigned)xn < (unsigned)HH){                                \
        float4 t4 = *(const float4*)(src + (size_t)xn*WW + gc);               \
        if (FIRST && tens == 0){                                              \
            t4.x = sigf(t4.x); t4.y = sigf(t4.y);                             \
            t4.z = sigf(t4.z); t4.w = sigf(t4.w);                             \
        }                                                                     \
        nxt[0]=t4.x; nxt[1]=t4.y; nxt[2]=t4.z; nxt[3]=t4.w;                   \
    } else {                                                                  \
        nxt[0]=PINF; nxt[1]=PINF; nxt[2]=PINF; nxt[3]=PINF;                   \
    }                                                                         \
    float o4[4];                                                              \
    STAGE(4, sN, sO, eN, eO, b3,  o4);                                        \
    STAGE(3, sN, sO, eN, eO, b2,  b3);                                        \
    STAGE(2, sN, sO, eN, eO, b1,  b2);                                        \
    STAGE(1, sN, sO, eN, eO, b0,  b1);                                        \
    STAGE(0, sN, sO, eN, eO, in0, b0);                                        \
    if (owned && (unsigned)(x - LAGOUT - r0) < (unsigned)RB){                 \
        *(float4*)(dst + (size_t)(x - LAGOUT)*WW + gc) =                      \
            make_float4(o4[0], o4[1], o4[2], o4[3]);                          \
    }                                                                         \
}

// ---------------- fused 5-iteration soft skeletonize pass ----------------
template<bool FIRST>
__global__ void __launch_bounds__(128, 3) k_skel(const float* __restrict__ logits,
                                                 const float* __restrict__ target){
    const float PINF = __int_as_float(0x7f800000);
    const float NINF = __int_as_float(0xff800000);

    int gw   = blockIdx.x * 4 + (threadIdx.x >> 5);
    int lane = threadIdx.x & 31;
    int band = gw & 3;  int q = gw >> 2;
    int ct   = q % CTILES; q /= CTILES;
    int img  = q & 31;  int tens = q >> 5;

    const float* __restrict__ src;
    float* __restrict__ dst;
    if (FIRST){
        src = (tens ? target : logits) + (size_t)img*NPIX;
        dst = g_tmp[tens] + (size_t)img*NPIX;
    } else {
        src = g_tmp[tens] + (size_t)img*NPIX;
        dst = g_skel[tens] + (size_t)img*NPIX;
    }

    int r0 = band * RB;
    int c0 = ct*OWNC - HALO_C;
    int gc = c0 + (lane<<2);                 // lane's 4 global cols (mult of 4)
    bool colok = (gc >= 0) && (gc < WW);     // whole float4 in or out
    bool owned = (lane >= HALO_C/4) && (lane < (HALO_C+OWNC)/4) && colok;

    // Ping-pong state per stage + one-step output buffers b0..b3
    float sA[KF][4], sB[KF][4], eA[KF][4], eB[KF][4];
    float b0[4], b1[4], b2[4], b3[4];
    #pragma unroll
    for (int j = 0; j < KF; j++)
        #pragma unroll
        for (int v = 0; v < 4; v++){
            sA[j][v]=PINF; sB[j][v]=PINF; eA[j][v]=NINF; eB[j][v]=NINF;
        }
    #pragma unroll
    for (int v = 0; v < 4; v++){ b0[v]=PINF; b1[v]=PINF; b2[v]=PINF; b3[v]=PINF; }

    int x0 = r0 - 11;

    // software-pipelined row fetch: nxt holds the row for the upcoming step
    float nxt[4];
    if (colok && (unsigned)x0 < (unsigned)HH){
        float4 t4 = *(const float4*)(src + (size_t)x0*WW + gc);
        if (FIRST && tens == 0){
            t4.x = sigf(t4.x); t4.y = sigf(t4.y);
            t4.z = sigf(t4.z); t4.w = sigf(t4.w);
        }
        nxt[0]=t4.x; nxt[1]=t4.y; nxt[2]=t4.z; nxt[3]=t4.w;
    } else {
        nxt[0]=PINF; nxt[1]=PINF; nxt[2]=PINF; nxt[3]=PINF;
    }

    for (int step = 0; step < NSTEPS; step += 2){
        DO_STEP(x0 + step,     sA, sB, eA, eB);
        DO_STEP(x0 + step + 1, sB, sA, eB, eA);
    }
}

// ---------------- final reduction ----------------
__global__ void k_fin(float* __restrict__ out){
    int i = threadIdx.x;   // 32 threads, one per image
    float d  = (2.0f*g_acc[i][2] + SMOOTHF) / (g_acc[i][0] + g_acc[i][1] + SMOOTHF);
    float sd = (2.0f*g_acc[i][5] + SMOOTHF) / (g_acc[i][3] + g_acc[i][4] + SMOOTHF);
    #pragma unroll
    for (int o=16;o;o>>=1){
        d  += __shfl_down_sync(ALLM, d , o);
        sd += __shfl_down_sync(ALLM, sd, o);
    }
    if (i == 0){
        float dice  = d  * (1.0f/32.0f);
        float sdice = sd * (1.0f/32.0f);
        out[0] = 0.5f*(1.0f - dice) + 0.5f*(1.0f - sdice);
        out[1] = dice;
        out[2] = sdice;
    }
}

extern "C" void kernel_launch(void* const* d_in, const int* in_sizes, int n_in,
                              void* d_out, int out_size){
    const float* logits = (const float*)d_in[0];
    const float* target = (const float*)d_in[1];
    float* out = (float*)d_out;

    int nwarps = 2 * NIMG * CTILES * NBANDS;       // 1280
    int nblocks = nwarps / 4;                      // 320

    k_init<<<1, 256>>>();
    k_dice<<<dim3(NIMG, 32), 256>>>(logits, target);
    k_skel<true ><<<nblocks, 128>>>(logits, target);
    k_skel<false><<<nblocks, 128>>>(logits, target);
    k_sdice<<<dim3(NIMG, 32), 256>>>();
    k_fin<<<1, 32>>>(out);
    (void)in_sizes; (void)n_in; (void)out_size;
}

// round 6
// speedup vs baseline: 1.3858x; 1.1271x over previous
#include <cuda_runtime.h>
#include <cuda_bf16.h>

#define HH 512
#define WW 512
#define NPIX (HH*WW)
#define NIMG 32
#define SMOOTHF 1e-5f
#define KF 5            // fused skeletonize iterations per pass
#define HALO_C 12       // column halo per side (>= 2*KF, multiple of 4)
#define OWNC 104        // owned columns per warp window (128 - 2*HALO_C)
#define CTILES 5        // ceil(512/104)
#define RB 128          // rows per band
#define NBANDS 4
#define LAGOUT 14       // output lag: 3*(KF-1)+2
#define NSTEPS 154      // RB + 25 + 1 (even, x0 = r0-11)
#define ALLM 0xffffffffu

// Scratch (device globals: no allocation allowed; zero-initialized at load)
__device__ float g_tmp [2][NIMG*NPIX];   // after iterations 1..5
__device__ float g_skel[2][NIMG*NPIX];   // after iterations 6..10
__device__ float g_acc [NIMG][8];        // 0:sp 1:st 2:spt 3:ssp 4:sst 5:sspt

__device__ __forceinline__ float sigf(float x){
    return __fdividef(1.0f, 1.0f + __expf(-x));
}

// ---------------- dice sums: sigmoid(logits) vs target ----------------
__global__ void k_dice(const float* __restrict__ logits, const float* __restrict__ target){
    int img = blockIdx.x;
    size_t base = (size_t)img*NPIX + (size_t)blockIdx.y*(NPIX/32);
    const float4* Lp = (const float4*)(logits + base);
    const float4* Tp = (const float4*)(target + base);
    int tid = threadIdx.x;
    float sp=0.f, st=0.f, spt=0.f;
    #pragma unroll
    for (int i = 0; i < 8; i++){
        float4 l = Lp[i*256 + tid];
        float4 t = Tp[i*256 + tid];
        float p;
        p = sigf(l.x); sp += p; st += t.x; spt += p*t.x;
        p = sigf(l.y); sp += p; st += t.y; spt += p*t.y;
        p = sigf(l.z); sp += p; st += t.z; spt += p*t.z;
        p = sigf(l.w); sp += p; st += t.w; spt += p*t.w;
    }
    #pragma unroll
    for (int o=16;o;o>>=1){
        sp  += __shfl_down_sync(ALLM, sp , o);
        st  += __shfl_down_sync(ALLM, st , o);
        spt += __shfl_down_sync(ALLM, spt, o);
    }
    if ((tid & 31) == 0){
        atomicAdd(&g_acc[img][0], sp);
        atomicAdd(&g_acc[img][1], st);
        atomicAdd(&g_acc[img][2], spt);
    }
}

// ---------------- skeleton dice sums ----------------
__global__ void k_sdice(){
    int img = blockIdx.x;
    size_t base = (size_t)img*NPIX + (size_t)blockIdx.y*(NPIX/32);
    const float4* Pp = (const float4*)(g_skel[0] + base);
    const float4* Tp = (const float4*)(g_skel[1] + base);
    int tid = threadIdx.x;
    float sp=0.f, st=0.f, spt=0.f;
    #pragma unroll
    for (int i = 0; i < 8; i++){
        float4 p = Pp[i*256 + tid];
        float4 t = Tp[i*256 + tid];
        sp  += (p.x+p.y)+(p.z+p.w);
        st  += (t.x+t.y)+(t.z+t.w);
        spt += (p.x*t.x + p.y*t.y) + (p.z*t.z + p.w*t.w);
    }
    #pragma unroll
    for (int o=16;o;o>>=1){
        sp  += __shfl_down_sync(ALLM, sp , o);
        st  += __shfl_down_sync(ALLM, st , o);
        spt += __shfl_down_sync(ALLM, spt, o);
    }
    if ((tid & 31) == 0){
        atomicAdd(&g_acc[img][3], sp);
        atomicAdd(&g_acc[img][4], st);
        atomicAdd(&g_acc[img][5], spt);
    }
}

// One decoupled pipeline stage j. Fed row xr = x - 3j (value in CIN).
// State: sN[j] = In_j[xr-1], sO[j] = In_j[xr-2], eN[j] = E_j[xr-2],
// eO[j] = E_j[xr-3]. Computes E_j[xr-1] and O_j[xr-2] -> OUT.
// Rotation by role swap (zero MOVs). Output is NOT boundary-forced: at
// OOB rows/cols it becomes +INF or NaN; fminf/fmaxf drop NaN operands, so
// downstream min chains treat it exactly as the +INF sentinel. Only the
// eroded field needs explicit forcing (en -> -INF at OOB), since it feeds
// a max-pool where the neutral element differs.
#define STAGE(j, sN, sO, eN, eO, CIN, OUT)                                    \
{                                                                             \
    float vm0 = fminf(sO[j][0], fminf(sN[j][0], CIN[0]));                     \
    float vm1 = fminf(sO[j][1], fminf(sN[j][1], CIN[1]));                     \
    float vm2 = fminf(sO[j][2], fminf(sN[j][2], CIN[2]));                     \
    float vm3 = fminf(sO[j][3], fminf(sN[j][3], CIN[3]));                     \
    float Lm = __shfl_up_sync  (ALLM, vm3, 1);                                \
    float Rm = __shfl_down_sync(ALLM, vm0, 1);                                \
    float m01 = fminf(vm0, vm1), m12 = fminf(vm1, vm2), m23 = fminf(vm2, vm3);\
    float en0 = fminf(Lm,  m01);                                              \
    float en1 = fminf(m01, vm2);                                              \
    float en2 = fminf(m12, vm3);                                              \
    float en3 = fminf(m23, Rm);                                               \
    if (!(colok && (unsigned)(x - 3*(j) - 1) < (unsigned)HH)){                \
        en0 = NINF; en1 = NINF; en2 = NINF; en3 = NINF;                       \
    }                                                                         \
    float tx0 = fmaxf(eO[j][0], fmaxf(eN[j][0], en0));                        \
    float tx1 = fmaxf(eO[j][1], fmaxf(eN[j][1], en1));                        \
    float tx2 = fmaxf(eO[j][2], fmaxf(eN[j][2], en2));                        \
    float tx3 = fmaxf(eO[j][3], fmaxf(eN[j][3], en3));                        \
    float Lx = __shfl_up_sync  (ALLM, tx3, 1);                                \
    float Rx = __shfl_down_sync(ALLM, tx0, 1);                                \
    float M01 = fmaxf(tx0, tx1), M12 = fmaxf(tx1, tx2), M23 = fmaxf(tx2, tx3);\
    float T0 = fmaxf(Lx,  M01);                                               \
    float T1 = fmaxf(M01, tx2);                                               \
    float T2 = fmaxf(M12, tx3);                                               \
    float T3 = fmaxf(M23, Rx);                                                \
    float o0 = fmaf(eN[j][0]-sO[j][0], T0, sO[j][0]);                         \
    float o1 = fmaf(eN[j][1]-sO[j][1], T1, sO[j][1]);                         \
    float o2 = fmaf(eN[j][2]-sO[j][2], T2, sO[j][2]);                         \
    float o3 = fmaf(eN[j][3]-sO[j][3], T3, sO[j][3]);                         \
    sO[j][0] = CIN[0]; sO[j][1] = CIN[1]; sO[j][2] = CIN[2]; sO[j][3] = CIN[3];\
    eO[j][0] = en0;    eO[j][1] = en1;    eO[j][2] = en2;    eO[j][3] = en3;  \
    OUT[0] = o0; OUT[1] = o1; OUT[2] = o2; OUT[3] = o3;                       \
}

// One full row-step. Stages evaluated in DESCENDING order so each stage j+1
// reads buf[j] (previous step's output of stage j) before stage j overwrites
// it. All 5 stages are mutually independent within a step -> ILP ~5.
#define DO_STEP(X, sN, sO, eN, eO)                                            \
{                                                                             \
    int x = (X);                                                              \
    float in0[4] = {nxt[0], nxt[1], nxt[2], nxt[3]};                          \
    int xn = x + 1;                                                           \
    if (colok && (unsigned)xn < (unsigned)HH){                                \
        float4 t4 = *(const float4*)(src + (size_t)xn*WW + gc);               \
        if (FIRST && tens == 0){                                              \
            t4.x = sigf(t4.x); t4.y = sigf(t4.y);                             \
            t4.z = sigf(t4.z); t4.w = sigf(t4.w);                             \
        }                                                                     \
        nxt[0]=t4.x; nxt[1]=t4.y; nxt[2]=t4.z; nxt[3]=t4.w;                   \
    } else {                                                                  \
        nxt[0]=PINF; nxt[1]=PINF; nxt[2]=PINF; nxt[3]=PINF;                   \
    }                                                                         \
    float o4[4];                                                              \
    STAGE(4, sN, sO, eN, eO, b3,  o4);                                        \
    STAGE(3, sN, sO, eN, eO, b2,  b3);                                        \
    STAGE(2, sN, sO, eN, eO, b1,  b2);                                        \
    STAGE(1, sN, sO, eN, eO, b0,  b1);                                        \
    STAGE(0, sN, sO, eN, eO, in0, b0);                                        \
    if (owned && (unsigned)(x - LAGOUT - r0) < (unsigned)RB){                 \
        *(float4*)(dst + (size_t)(x - LAGOUT)*WW + gc) =                      \
            make_float4(o4[0], o4[1], o4[2], o4[3]);                          \
    }                                                                         \
}

// ---------------- fused 5-iteration soft skeletonize pass ----------------
// Single-warp blocks for fine-grained SM load balance (1280 blocks / 148 SMs
// -> 9 vs 8 warps per SM instead of 12 vs 8 with 4-warp blocks).
template<bool FIRST>
__global__ void __launch_bounds__(32, 12) k_skel(const float* __restrict__ logits,
                                                 const float* __restrict__ target){
    const float PINF = __int_as_float(0x7f800000);
    const float NINF = __int_as_float(0xff800000);

    int gw   = blockIdx.x;
    int lane = threadIdx.x;
    int band = gw & 3;  int q = gw >> 2;
    int ct   = q % CTILES; q /= CTILES;
    int img  = q & 31;  int tens = q >> 5;

    const float* __restrict__ src;
    float* __restrict__ dst;
    if (FIRST){
        src = (tens ? target : logits) + (size_t)img*NPIX;
        dst = g_tmp[tens] + (size_t)img*NPIX;
    } else {
        src = g_tmp[tens] + (size_t)img*NPIX;
        dst = g_skel[tens] + (size_t)img*NPIX;
    }

    int r0 = band * RB;
    int c0 = ct*OWNC - HALO_C;
    int gc = c0 + (lane<<2);                 // lane's 4 global cols (mult of 4)
    bool colok = (gc >= 0) && (gc < WW);     // whole float4 in or out
    bool owned = (lane >= HALO_C/4) && (lane < (HALO_C+OWNC)/4) && colok;

    // Ping-pong state per stage + one-step output buffers b0..b3
    float sA[KF][4], sB[KF][4], eA[KF][4], eB[KF][4];
    float b0[4], b1[4], b2[4], b3[4];
    #pragma unroll
    for (int j = 0; j < KF; j++)
        #pragma unroll
        for (int v = 0; v < 4; v++){
            sA[j][v]=PINF; sB[j][v]=PINF; eA[j][v]=NINF; eB[j][v]=NINF;
        }
    #pragma unroll
    for (int v = 0; v < 4; v++){ b0[v]=PINF; b1[v]=PINF; b2[v]=PINF; b3[v]=PINF; }

    int x0 = r0 - 11;

    // software-pipelined row fetch: nxt holds the row for the upcoming step
    float nxt[4];
    if (colok && (unsigned)x0 < (unsigned)HH){
        float4 t4 = *(const float4*)(src + (size_t)x0*WW + gc);
        if (FIRST && tens == 0){
            t4.x = sigf(t4.x); t4.y = sigf(t4.y);
            t4.z = sigf(t4.z); t4.w = sigf(t4.w);
        }
        nxt[0]=t4.x; nxt[1]=t4.y; nxt[2]=t4.z; nxt[3]=t4.w;
    } else {
        nxt[0]=PINF; nxt[1]=PINF; nxt[2]=PINF; nxt[3]=PINF;
    }

    for (int step = 0; step < NSTEPS; step += 2){
        DO_STEP(x0 + step,     sA, sB, eA, eB);
        DO_STEP(x0 + step + 1, sB, sA, eB, eA);
    }
}

// ---------------- final reduction (also re-zeroes accumulators) ----------------
__global__ void k_fin(float* __restrict__ out){
    int i = threadIdx.x;   // 32 threads, one per image
    float d  = (2.0f*g_acc[i][2] + SMOOTHF) / (g_acc[i][0] + g_acc[i][1] + SMOOTHF);
    float sd = (2.0f*g_acc[i][5] + SMOOTHF) / (g_acc[i][3] + g_acc[i][4] + SMOOTHF);
    #pragma unroll
    for (int o=16;o;o>>=1){
        d  += __shfl_down_sync(ALLM, d , o);
        sd += __shfl_down_sync(ALLM, sd, o);
    }
    if (i == 0){
        float dice  = d  * (1.0f/32.0f);
        float sdice = sd * (1.0f/32.0f);
        out[0] = 0.5f*(1.0f - dice) + 0.5f*(1.0f - sdice);
        out[1] = dice;
        out[2] = sdice;
    }
    // reset accumulators for the next graph replay (globals start zeroed at
    // module load, so the invariant "g_acc == 0 on entry" always holds)
    #pragma unroll
    for (int v = 0; v < 8; v++) g_acc[i][v] = 0.0f;
}

extern "C" void kernel_launch(void* const* d_in, const int* in_sizes, int n_in,
                              void* d_out, int out_size){
    const float* logits = (const float*)d_in[0];
    const float* target = (const float*)d_in[1];
    float* out = (float*)d_out;

    int nblocks = 2 * NIMG * CTILES * NBANDS;      // 1280 single-warp blocks

    k_dice<<<dim3(NIMG, 32), 256>>>(logits, target);
    k_skel<true ><<<nblocks, 32>>>(logits, target);
    k_skel<false><<<nblocks, 32>>>(logits, target);
    k_sdice<<<dim3(NIMG, 32), 256>>>();
    k_fin<<<1, 32>>>(out);
    (void)in_sizes; (void)n_in; (void)out_size;
}